// round 8
// baseline (speedup 1.0000x reference)
#include <cuda_runtime.h>
#include <cuda_bf16.h>
#include <cstdint>

// Problem constants
#define C_CH   1024
#define H_     100
#define W_     50
#define NROI   256
#define NCLS   21
#define KDIM   50176            // 1024 * 49
#define FCOUT  1024
#define ZSPLIT 16
#define KCHUNK (KDIM / ZSPLIT)  // 3136
#define BKK    32               // K per smem stage
#define NIT    (KCHUNK / BKK)   // 98
#define BM     128
#define BN     128
#define NSTG   3                // cp.async ring depth

// smem stage layout: 4 tiles of 128 rows x 32 bf16 (64B rows, XOR swizzled)
#define TS_AH   0
#define TS_AL   8192
#define TS_BH   16384
#define TS_BL   24576
#define STAGE_B 32768
#define SMEM_DYN (NSTG * STAGE_B)   // 98304

// Scratch (__device__ globals: no cudaMalloc allowed)
__device__ __align__(256) __nv_bfloat16 g_ah[NROI * KDIM];
__device__ __align__(256) __nv_bfloat16 g_al[NROI * KDIM];
__device__ __align__(256) __nv_bfloat16 g_bh[FCOUT * KDIM];
__device__ __align__(256) __nv_bfloat16 g_bl[FCOUT * KDIM];
__device__ float g_part[ZSPLIT * NROI * FCOUT];
__device__ float g_r[NROI * FCOUT];

// ---------------------------------------------------------------------------
// Kernel 1: ROI adaptive max-pool 7x7 -> hi/lo bf16 split
// ---------------------------------------------------------------------------
__global__ void pool_kernel(const float* __restrict__ fmap,
                            const int*   __restrict__ props)
{
    int roi = blockIdx.y;
    int idx = blockIdx.x * blockDim.x + threadIdx.x;
    if (idx >= KDIM) return;

    int x1 = props[roi * 4 + 0];
    int y1 = props[roi * 4 + 1];
    int x2 = props[roi * 4 + 2];
    int y2 = props[roi * 4 + 3];
    int h0 = max(x1, 0) >> 4;
    int w0 = max(y1, 0) >> 4;
    int h1 = max(x2, 0) >> 4;
    int w1 = max(y2, 0) >> 4;
    int sh = h1 - h0 + 1;
    int sw = w1 - w0 + 1;

    int c = idx / 49;
    int p = idx - c * 49;
    int i = p / 7;
    int j = p - i * 7;

    int hs = h0 + (i * sh) / 7;
    int he = h0 + ((i + 1) * sh + 6) / 7;
    int ws = w0 + (j * sw) / 7;
    int we = w0 + ((j + 1) * sw + 6) / 7;

    const float* base = fmap + (size_t)c * (H_ * W_);
    float m = -3.402823466e38f;
    for (int hh = hs; hh < he; ++hh) {
        const float* rowp = base + hh * W_;
        for (int ww = ws; ww < we; ++ww)
            m = fmaxf(m, __ldg(rowp + ww));
    }
    size_t off = (size_t)roi * KDIM + idx;
    __nv_bfloat16 h = __float2bfloat16(m);
    __nv_bfloat16 l = __float2bfloat16(m - __bfloat162float(h));
    g_ah[off] = h;
    g_al[off] = l;
}

// ---------------------------------------------------------------------------
// Kernel 1b: fc_w fp32 -> hi/lo bf16 split
// ---------------------------------------------------------------------------
__global__ void convert_w(const float4* __restrict__ w)
{
    size_t i = (size_t)blockIdx.x * blockDim.x + threadIdx.x;
    float4 v = w[i];
    __nv_bfloat16 h0 = __float2bfloat16(v.x);
    __nv_bfloat16 h1 = __float2bfloat16(v.y);
    __nv_bfloat16 h2 = __float2bfloat16(v.z);
    __nv_bfloat16 h3 = __float2bfloat16(v.w);
    __nv_bfloat16 l0 = __float2bfloat16(v.x - __bfloat162float(h0));
    __nv_bfloat16 l1 = __float2bfloat16(v.y - __bfloat162float(h1));
    __nv_bfloat16 l2 = __float2bfloat16(v.z - __bfloat162float(h2));
    __nv_bfloat16 l3 = __float2bfloat16(v.w - __bfloat162float(h3));
    __nv_bfloat162* bh = (__nv_bfloat162*)g_bh;
    __nv_bfloat162* bl = (__nv_bfloat162*)g_bl;
    bh[i * 2 + 0] = __nv_bfloat162(h0, h1);
    bh[i * 2 + 1] = __nv_bfloat162(h2, h3);
    bl[i * 2 + 0] = __nv_bfloat162(l0, l1);
    bl[i * 2 + 1] = __nv_bfloat162(l2, l3);
}

// ---------------------------------------------------------------------------
// Kernel 2: bf16x3 mma.sync GEMM v3.
// 128x128 block, 8 warps (2m x 4n), warp tile 64x32, BK=32.
// 3-stage cp.async ring, ONE __syncthreads per iteration.
// A-fragment registers reused for ah then al -> peak live regs < 128 (occ 2).
// ---------------------------------------------------------------------------
__device__ __forceinline__ void mma16816(float* c, const uint32_t* a, const uint32_t* b)
{
    asm volatile(
        "mma.sync.aligned.m16n8k16.row.col.f32.bf16.bf16.f32 "
        "{%0,%1,%2,%3}, {%4,%5,%6,%7}, {%8,%9}, {%0,%1,%2,%3};\n"
        : "+f"(c[0]), "+f"(c[1]), "+f"(c[2]), "+f"(c[3])
        : "r"(a[0]), "r"(a[1]), "r"(a[2]), "r"(a[3]), "r"(b[0]), "r"(b[1]));
}

__device__ __forceinline__ void ldm4(uint32_t* r, uint32_t addr)
{
    asm volatile("ldmatrix.sync.aligned.m8n8.x4.shared.b16 {%0,%1,%2,%3}, [%4];"
                 : "=r"(r[0]), "=r"(r[1]), "=r"(r[2]), "=r"(r[3]) : "r"(addr));
}

__global__ void __launch_bounds__(256, 2)
gemm_mma()
{
    extern __shared__ char dynsm[];
    const uint32_t dynb = (uint32_t)__cvta_generic_to_shared(dynsm);

    const int tid  = threadIdx.x;
    const int warp = tid >> 5;
    const int lane = tid & 31;
    const int n0 = blockIdx.x * BN;
    const int m0 = blockIdx.y * BM;
    const int z  = blockIdx.z;
    const int k0 = z * KCHUNK;

    // ---- global->shared mapping (identical to proven v2) ----
    const int rbase = tid >> 2;          // 0..63
    const int chunk = tid & 3;
    const uint32_t swz16 = (uint32_t)((chunk ^ ((rbase >> 1) & 3)) << 4);

    const __nv_bfloat16* tb[4] = {
        g_ah + (size_t)m0 * KDIM + k0 + chunk * 8,
        g_al + (size_t)m0 * KDIM + k0 + chunk * 8,
        g_bh + (size_t)n0 * KDIM + k0 + chunk * 8,
        g_bl + (size_t)n0 * KDIM + k0 + chunk * 8
    };
    const uint32_t toff[4] = {TS_AH, TS_AL, TS_BH, TS_BL};

#define LOAD_STAGE(stg, koff)                                                   \
    do {                                                                        \
        _Pragma("unroll")                                                       \
        for (int _s = 0; _s < 8; ++_s) {                                        \
            int _row = rbase + 64 * (_s & 1);                                   \
            uint32_t _d = dynb + (stg) * STAGE_B + toff[_s >> 1] +              \
                          (uint32_t)(_row * 64) + swz16;                        \
            const __nv_bfloat16* _g = tb[_s >> 1] + (size_t)_row * KDIM + (koff);\
            asm volatile("cp.async.cg.shared.global [%0], [%1], 16;"            \
                         :: "r"(_d), "l"(_g) : "memory");                       \
        }                                                                       \
        asm volatile("cp.async.commit_group;" ::: "memory");                    \
    } while (0)

    // ---- per-warp fragment addressing ----
    const int wm = (warp & 1) * 64;
    const int wn = (warp >> 1) * 32;

    uint32_t aOff[4], aXr[4], bOff[2], bXr[2];
#pragma unroll
    for (int f = 0; f < 4; ++f) {
        int r = wm + f * 16 + (lane & 15);
        aOff[f] = (uint32_t)(r * 64);
        aXr[f]  = (uint32_t)((r >> 1) & 3);
    }
#pragma unroll
    for (int g = 0; g < 2; ++g) {
        int n = wn + g * 16 + (lane & 7) + ((lane >> 4) << 3);
        bOff[g] = (uint32_t)(n * 64);
        bXr[g]  = (uint32_t)((n >> 1) & 3);
    }
    const uint32_t aCk = (uint32_t)(lane >> 4);        // 0/1: k8 half for A
    const uint32_t bCk = (uint32_t)((lane >> 3) & 1);  // 0/1: k8 half for B

    float acc[4][4][4];
#pragma unroll
    for (int f = 0; f < 4; ++f)
#pragma unroll
        for (int nf = 0; nf < 4; ++nf)
#pragma unroll
            for (int q = 0; q < 4; ++q) acc[f][nf][q] = 0.f;

    // prologue: fill stages 0,1 (iterations 0,1)
    LOAD_STAGE(0, 0);
    LOAD_STAGE(1, BKK);

    int stage = 0;   // stage holding current iteration's data

    for (int it = 0; it < NIT; ++it) {
        // complete group 'it' (stage 'stage'): after this wait, groups <= it done
        if (it + 2 < NIT)
            asm volatile("cp.async.wait_group 1;" ::: "memory");
        else
            asm volatile("cp.async.wait_group 0;" ::: "memory");
        // Single barrier: publishes stage 'stage' to all warps AND proves all
        // warps finished computing iter it-1 -> its stage ((stage+2)%3) is free.
        __syncthreads();

        // prefetch iteration it+2 into stage (stage+2)%3
        if (it + 2 < NIT) {
            int tstage = stage + 2; if (tstage >= NSTG) tstage -= NSTG;
            LOAD_STAGE(tstage, (it + 2) * BKK);
        }

        const uint32_t sb = dynb + stage * STAGE_B;
#pragma unroll
        for (int ks = 0; ks < 2; ++ks) {
            const uint32_t ck = (uint32_t)(ks * 2);

            uint32_t fa[4][4];   // A fragments: ah now, al later (reused)
            uint32_t fbh[2][4];  // bh
            uint32_t fbl[2][4];  // bl

#pragma unroll
            for (int g = 0; g < 2; ++g)
                ldm4(fbh[g], sb + TS_BH + bOff[g] + (((ck + bCk) ^ bXr[g]) << 4));
#pragma unroll
            for (int f = 0; f < 4; ++f)
                ldm4(fa[f], sb + TS_AH + aOff[f] + (((ck + aCk) ^ aXr[f]) << 4));
#pragma unroll
            for (int f = 0; f < 4; ++f)
#pragma unroll
                for (int g = 0; g < 2; ++g) {
                    mma16816(acc[f][g * 2 + 0], fa[f], &fbh[g][0]);
                    mma16816(acc[f][g * 2 + 1], fa[f], &fbh[g][2]);
                }

#pragma unroll
            for (int g = 0; g < 2; ++g)
                ldm4(fbl[g], sb + TS_BL + bOff[g] + (((ck + bCk) ^ bXr[g]) << 4));
#pragma unroll
            for (int f = 0; f < 4; ++f)
#pragma unroll
                for (int g = 0; g < 2; ++g) {
                    mma16816(acc[f][g * 2 + 0], fa[f], &fbl[g][0]);
                    mma16816(acc[f][g * 2 + 1], fa[f], &fbl[g][2]);
                }

            // ah dead: reuse fa for al
#pragma unroll
            for (int f = 0; f < 4; ++f)
                ldm4(fa[f], sb + TS_AL + aOff[f] + (((ck + aCk) ^ aXr[f]) << 4));
#pragma unroll
            for (int f = 0; f < 4; ++f)
#pragma unroll
                for (int g = 0; g < 2; ++g) {
                    mma16816(acc[f][g * 2 + 0], fa[f], &fbh[g][0]);
                    mma16816(acc[f][g * 2 + 1], fa[f], &fbh[g][2]);
                }
        }

        if (++stage >= NSTG) stage = 0;
    }

    // ---- epilogue: acc -> g_part[z] ----
    float* op = g_part + (size_t)z * (NROI * FCOUT);
#pragma unroll
    for (int f = 0; f < 4; ++f) {
        int r = m0 + wm + f * 16 + (lane >> 2);
#pragma unroll
        for (int nf = 0; nf < 4; ++nf) {
            int c = n0 + wn + nf * 8 + (lane & 3) * 2;
            *(float2*)&op[(size_t)r * FCOUT + c] =
                make_float2(acc[f][nf][0], acc[f][nf][1]);
            *(float2*)&op[(size_t)(r + 8) * FCOUT + c] =
                make_float2(acc[f][nf][2], acc[f][nf][3]);
        }
    }
#undef LOAD_STAGE
}

// ---------------------------------------------------------------------------
// Kernel 3: reduce ZSPLIT partials + bias + ReLU
// ---------------------------------------------------------------------------
__global__ void reduce_bias_relu(const float* __restrict__ fc_b)
{
    int idx = blockIdx.x * blockDim.x + threadIdx.x;
    float s = __ldg(fc_b + (idx & (FCOUT - 1)));
#pragma unroll
    for (int zz = 0; zz < ZSPLIT; ++zz)
        s += g_part[(size_t)zz * (NROI * FCOUT) + idx];
    g_r[idx] = fmaxf(s, 0.f);
}

// ---------------------------------------------------------------------------
// Kernel 4: cls/reg heads
// ---------------------------------------------------------------------------
__global__ void heads_kernel(const float* __restrict__ cls_w,
                             const float* __restrict__ cls_b,
                             const float* __restrict__ reg_w,
                             const float* __restrict__ reg_b,
                             float* __restrict__ out)
{
    const int roi = blockIdx.x;
    __shared__ float sr[FCOUT];
    __shared__ float scls[NCLS];
    __shared__ int   sbest;

    const int tid  = threadIdx.x;
    const int warp = tid >> 5;
    const int lane = tid & 31;

    for (int i = tid; i < FCOUT; i += 256)
        sr[i] = g_r[(size_t)roi * FCOUT + i];
    __syncthreads();

    for (int cl = warp; cl < NCLS; cl += 8) {
        const float* w = cls_w + (size_t)cl * FCOUT;
        float s = 0.f;
        for (int k = lane; k < FCOUT; k += 32)
            s = fmaf(sr[k], __ldg(w + k), s);
#pragma unroll
        for (int o = 16; o > 0; o >>= 1) s += __shfl_xor_sync(0xFFFFFFFFu, s, o);
        if (lane == 0) {
            s += __ldg(cls_b + cl);
            scls[cl] = s;
            out[(size_t)roi * NCLS + cl] = s;
        }
    }
    __syncthreads();

    if (tid == 0) {
        float best = scls[0];
        int bi = 0;
        for (int c2 = 1; c2 < NCLS; ++c2)
            if (scls[c2] > best) { best = scls[c2]; bi = c2; }
        sbest = bi;
    }
    __syncthreads();

    const int best = sbest;
    if (warp < 4) {
        const float* w = reg_w + (size_t)(best * 4 + warp) * FCOUT;
        float s = 0.f;
        for (int k = lane; k < FCOUT; k += 32)
            s = fmaf(sr[k], __ldg(w + k), s);
#pragma unroll
        for (int o = 16; o > 0; o >>= 1) s += __shfl_xor_sync(0xFFFFFFFFu, s, o);
        if (lane == 0)
            out[NROI * NCLS + roi * 4 + warp] = s + __ldg(reg_b + best * 4 + warp);
    }
}

// ---------------------------------------------------------------------------
// Launch
// ---------------------------------------------------------------------------
extern "C" void kernel_launch(void* const* d_in, const int* in_sizes, int n_in,
                              void* d_out, int out_size)
{
    const float* fmap  = (const float*)d_in[0];
    const int*   props = (const int*)  d_in[1];
    const float* fc_w  = (const float*)d_in[2];
    const float* fc_b  = (const float*)d_in[3];
    const float* cls_w = (const float*)d_in[4];
    const float* cls_b = (const float*)d_in[5];
    const float* reg_w = (const float*)d_in[6];
    const float* reg_b = (const float*)d_in[7];
    float* out = (float*)d_out;

    cudaFuncSetAttribute(gemm_mma,
                         cudaFuncAttributeMaxDynamicSharedMemorySize, SMEM_DYN);

    // 1) fc_w split
    convert_w<<<(FCOUT * KDIM / 4) / 256, 256>>>((const float4*)fc_w);

    // 2) ROI pool -> hi/lo bf16
    dim3 pg((KDIM + 255) / 256, NROI);
    pool_kernel<<<pg, 256>>>(fmap, props);

    // 3) mma.sync GEMM v3: 8 N-blocks x 2 M-blocks x 16 K-splits = 256 blocks
    dim3 gg(FCOUT / BN, NROI / BM, ZSPLIT);
    gemm_mma<<<gg, 256, SMEM_DYN>>>();

    // 4) reduce + bias + relu
    reduce_bias_relu<<<(NROI * FCOUT) / 256, 256>>>(fc_b);

    // 5) heads
    heads_kernel<<<NROI, 256>>>(cls_w, cls_b, reg_w, reg_b, out);
}